// round 10
// baseline (speedup 1.0000x reference)
#include <cuda_runtime.h>

#define NB     4
#define NPTS   8192
#define TPB    128
#define TQ     4
#define QB     (TPB*TQ)       // 512 queries per block
#define MC     512            // targets per block chunk (256 pairs)
#define ASZ    (NB*NPTS)      // 32768 points per array

// Scratch (static device globals, zero-initialized at module load; no allocations):
// g_enc semantics: u = ~fenc(min_e). 0 == +inf identity for atomicMax.
// reduce_kernel resets consumed entries to 0 => identical state for every graph replay.
__device__ unsigned g_enc[2*ASZ];    // [dir][point]; dir=0: array1 queries
__device__ float    g_part[256];
__device__ unsigned g_ticket;        // zero-init; self-resetting

__device__ __forceinline__ unsigned long long pk2(float lo, float hi) {
    unsigned long long r;
    asm("mov.b64 %0, {%1,%2};" : "=l"(r) : "f"(lo), "f"(hi));
    return r;
}
// Order-preserving float->uint (increasing): fenc. We atomicMax on ~fenc.
__device__ __forceinline__ unsigned fenc(float f) {
    unsigned b = __float_as_uint(f);
    return b ^ ((b & 0x80000000u) ? 0xFFFFFFFFu : 0x80000000u);
}
__device__ __forceinline__ float fdec(unsigned u) {   // inverse of fenc
    unsigned b = (u & 0x80000000u) ? (u ^ 0x80000000u) : ~u;
    return __uint_as_float(b);
}

// Fused both directions, prep-free: blockIdx.z=(batch<<1)|dir, grid (16,16,8)=2048.
// dir=0: queries=array1, targets=array2; dir=1: queries=array2, targets=array1.
// Each block: (a) transforms its raw 512-target chunk into packed pair layout in
// shared, (b) stages its 512 queries in shared, (c) runs the proven TQ=4 FFMA2 loop.
__global__ __launch_bounds__(TPB) void pass_kernel(const float* __restrict__ q1,
                                                   const float* __restrict__ q2) {
    int dir = blockIdx.z & 1;
    int b   = blockIdx.z >> 1;
    const float* qraw   = dir ? q2 : q1;
    const float* traw   = dir ? q1 : q2;
    unsigned*    encOut = g_enc + dir * ASZ;

    __shared__ float4 tsh[MC];        // 8 KB packed targets: 256 pairs * 2 float4
    __shared__ float  qsh[QB * 3];    // 6 KB staged queries

    int t  = threadIdx.x;
    int q0 = b * NPTS + blockIdx.x * QB;

    // (a) target transform: 12 floats (4 points = 2 pairs) per thread, coalesced.
    {
        const float4* tsrc = (const float4*)(traw + (size_t)(b * NPTS + blockIdx.y * MC) * 3);
        float4 A = tsrc[3*t], B = tsrc[3*t + 1], C = tsrc[3*t + 2];
        // points 4t..4t+3: (A.x,A.y,A.z) (A.w,B.x,B.y) (B.z,B.w,C.x) (C.y,C.z,C.w)
        float h0 = 0.5f*(A.x*A.x + A.y*A.y + A.z*A.z);
        float h1 = 0.5f*(A.w*A.w + B.x*B.x + B.y*B.y);
        float h2 = 0.5f*(B.z*B.z + B.w*B.w + C.x*C.x);
        float h3 = 0.5f*(C.y*C.y + C.z*C.z + C.w*C.w);
        tsh[4*t    ] = make_float4(-A.x, -A.w, -A.y, -B.x);   // pair 2t:   -x0,-x1,-y0,-y1
        tsh[4*t + 1] = make_float4(-A.z, -B.y,  h0,   h1);    //            -z0,-z1, h0, h1
        tsh[4*t + 2] = make_float4(-B.z, -C.y, -B.w, -C.z);   // pair 2t+1
        tsh[4*t + 3] = make_float4(-C.x, -C.w,  h2,   h3);
    }
    // (b) query staging: 512 queries * 3 floats = 384 float4, coalesced.
    {
        const float4* qsrc = (const float4*)(qraw + (size_t)q0 * 3);
        float4* qdst = (float4*)qsh;
#pragma unroll
        for (int i = 0; i < 3; i++) qdst[t + i * TPB] = qsrc[t + i * TPB];
    }
    __syncthreads();

    unsigned long long X2[TQ], Y2[TQ], Z2[TQ];
    float mnlo[TQ], mnhi[TQ];
#pragma unroll
    for (int k = 0; k < TQ; k++) {
        int qi = t + k * TPB;                 // stride-3 LDS: gcd(3,32)=1, conflict-free
        float x = qsh[3*qi], y = qsh[3*qi+1], z = qsh[3*qi+2];
        X2[k] = pk2(x, x); Y2[k] = pk2(y, y); Z2[k] = pk2(z, z);
        mnlo[k] = __int_as_float(0x7f800000);
        mnhi[k] = __int_as_float(0x7f800000);
    }

#pragma unroll 2
    for (int p = 0; p < MC / 2; ++p) {
        float4 A  = tsh[2*p];
        float4 Bv = tsh[2*p + 1];
        unsigned long long NX = pk2(A.x,  A.y);
        unsigned long long NY = pk2(A.z,  A.w);
        unsigned long long NZ = pk2(Bv.x, Bv.y);
        unsigned long long H  = pk2(Bv.z, Bv.w);
        unsigned long long acc[TQ];
        // e = h - (xq*xt + yq*yt + zq*zt), two targets per packed op.
#pragma unroll
        for (int k = 0; k < TQ; k++)
            asm("fma.rn.f32x2 %0, %1, %2, %3;" : "=l"(acc[k]) : "l"(Z2[k]), "l"(NZ), "l"(H));
#pragma unroll
        for (int k = 0; k < TQ; k++)
            asm("fma.rn.f32x2 %0, %1, %2, %0;" : "+l"(acc[k]) : "l"(Y2[k]), "l"(NY));
#pragma unroll
        for (int k = 0; k < TQ; k++)
            asm("fma.rn.f32x2 %0, %1, %2, %0;" : "+l"(acc[k]) : "l"(X2[k]), "l"(NX));
#pragma unroll
        for (int k = 0; k < TQ; k++) {
            float lo, hi;
            asm("mov.b64 {%0,%1}, %2;" : "=f"(lo), "=f"(hi) : "l"(acc[k]));
            mnlo[k] = fminf(mnlo[k], lo);
            mnhi[k] = fminf(mnhi[k], hi);
        }
    }

#pragma unroll
    for (int k = 0; k < TQ; k++)
        atomicMax(&encOut[q0 + t + k * TPB],
                  ~fenc(fminf(mnlo[k], mnhi[k])));
}

// Wide fused reduce: 256 blocks x 256 threads, exactly ONE enc entry per thread
// (all loads independent -> MLP>=4, latency overlapped). dist = a^2 + 2*e.
// Resets enc to 0 for the next graph replay. Ticket-fold, deterministic order.
__global__ void reduce_kernel(const float* __restrict__ q1,
                              const float* __restrict__ q2,
                              float* __restrict__ out) {
    int t   = threadIdx.x;
    int idx = blockIdx.x * 256 + t;            // 0..65535 = dir*32768 + pid
    int which = idx >> 15;
    int pid   = idx & (ASZ - 1);
    const float* raw = which ? q2 : q1;        // dir pairs with its query array

    unsigned u = g_enc[idx];
    float x = raw[3*pid], y = raw[3*pid+1], z = raw[3*pid+2];
    g_enc[idx] = 0u;                           // reset for next graph replay
    float s = (x*x + y*y + z*z) + 2.0f * fdec(~u);

#pragma unroll
    for (int o = 16; o > 0; o >>= 1) s += __shfl_down_sync(0xFFFFFFFFu, s, o);
    __shared__ float ws[8];
    __shared__ unsigned s_tk;
    if ((t & 31) == 0) ws[t >> 5] = s;
    __syncthreads();
    if (t == 0) {
        float bs = ((ws[0] + ws[1]) + (ws[2] + ws[3]))
                 + ((ws[4] + ws[5]) + (ws[6] + ws[7]));
        g_part[blockIdx.x] = bs;
        __threadfence();
        s_tk = atomicAdd(&g_ticket, 1u);
    }
    __syncthreads();

    if (s_tk == 255u && t < 32) {              // last block folds 256 partials
        __threadfence();
        float v = 0.f;
#pragma unroll
        for (int j = 0; j < 8; j++) v += g_part[t + 32*j];
#pragma unroll
        for (int o = 16; o > 0; o >>= 1) v += __shfl_down_sync(0xFFFFFFFFu, v, o);
        if (t == 0) {
            out[0] = v * (1.0f / (float)(NB * NPTS));
            g_ticket = 0u;                     // reset for next graph replay
        }
    }
}

extern "C" void kernel_launch(void* const* d_in, const int* in_sizes, int n_in,
                              void* d_out, int out_size) {
    const float* a1 = (const float*)d_in[0];   // array1 [4,8192,3]
    const float* a2 = (const float*)d_in[1];   // array2 [4,8192,3]
    float* out = (float*)d_out;

    dim3 grid(NPTS / QB, NPTS / MC, 2 * NB);   // (16,16,8) = 2048 blocks
    pass_kernel<<<grid, TPB>>>(a1, a2);
    reduce_kernel<<<256, 256>>>(a1, a2, out);
}

// round 11
// speedup vs baseline: 1.0227x; 1.0227x over previous
#include <cuda_runtime.h>

#define NB     4
#define NPTS   8192
#define TPB    128
#define TQ     4
#define QB     (TPB*TQ)       // 512 queries per block
#define MC     512            // targets per block chunk (256 pairs)
#define ASZ    (NB*NPTS)      // 32768 points per array
#define NCTA   2048           // pass grid size
#define NSLICE 64             // reduction slices (done by last 64 CTAs)

// Scratch (static device globals, zero-initialized at module load; no allocations):
// g_enc semantics: u = ~fenc(min_e). 0 == +inf identity for atomicMax.
// The reduction slices reset consumed entries to 0 => identical state every replay.
__device__ unsigned g_enc[2*ASZ];    // [dir][point]; dir=0: array1 queries
__device__ float    g_part[NSLICE];
__device__ unsigned g_tk1, g_tk2;    // zero-init; self-resetting tickets

__device__ __forceinline__ unsigned long long pk2(float lo, float hi) {
    unsigned long long r;
    asm("mov.b64 %0, {%1,%2};" : "=l"(r) : "f"(lo), "f"(hi));
    return r;
}
// Order-preserving float->uint (increasing): fenc. We atomicMax on ~fenc.
__device__ __forceinline__ unsigned fenc(float f) {
    unsigned b = __float_as_uint(f);
    return b ^ ((b & 0x80000000u) ? 0xFFFFFFFFu : 0x80000000u);
}
__device__ __forceinline__ float fdec(unsigned u) {   // inverse of fenc
    unsigned b = (u & 0x80000000u) ? (u ^ 0x80000000u) : ~u;
    return __uint_as_float(b);
}

// ONE kernel: fused both directions + in-tile prep + grid-wide ticket reduction.
// blockIdx.z=(batch<<1)|dir, grid (16,16,8)=2048 CTAs.
// dir=0: queries=array1, targets=array2; dir=1: queries=array2, targets=array1.
__global__ __launch_bounds__(TPB) void chamfer_kernel(const float* __restrict__ q1,
                                                      const float* __restrict__ q2,
                                                      float* __restrict__ out) {
    int dir = blockIdx.z & 1;
    int b   = blockIdx.z >> 1;
    const float* qraw   = dir ? q2 : q1;
    const float* traw   = dir ? q1 : q2;
    unsigned*    encOut = g_enc + dir * ASZ;

    __shared__ float4   tsh[MC];        // 8 KB packed targets: 256 pairs * 2 float4
    __shared__ float    qsh[QB * 3];    // 6 KB staged queries
    __shared__ float    ws[4];
    __shared__ unsigned s_tk;

    int t  = threadIdx.x;
    int q0 = b * NPTS + blockIdx.x * QB;

    // (a) target transform: 12 floats (4 points = 2 pairs) per thread, coalesced.
    {
        const float4* tsrc = (const float4*)(traw + (size_t)(b * NPTS + blockIdx.y * MC) * 3);
        float4 A = tsrc[3*t], B = tsrc[3*t + 1], C = tsrc[3*t + 2];
        // points 4t..4t+3: (A.x,A.y,A.z) (A.w,B.x,B.y) (B.z,B.w,C.x) (C.y,C.z,C.w)
        float h0 = 0.5f*(A.x*A.x + A.y*A.y + A.z*A.z);
        float h1 = 0.5f*(A.w*A.w + B.x*B.x + B.y*B.y);
        float h2 = 0.5f*(B.z*B.z + B.w*B.w + C.x*C.x);
        float h3 = 0.5f*(C.y*C.y + C.z*C.z + C.w*C.w);
        tsh[4*t    ] = make_float4(-A.x, -A.w, -A.y, -B.x);   // pair 2t:   -x0,-x1,-y0,-y1
        tsh[4*t + 1] = make_float4(-A.z, -B.y,  h0,   h1);    //            -z0,-z1, h0, h1
        tsh[4*t + 2] = make_float4(-B.z, -C.y, -B.w, -C.z);   // pair 2t+1
        tsh[4*t + 3] = make_float4(-C.x, -C.w,  h2,   h3);
    }
    // (b) query staging: 512 queries * 3 floats = 384 float4, coalesced.
    {
        const float4* qsrc = (const float4*)(qraw + (size_t)q0 * 3);
        float4* qdst = (float4*)qsh;
#pragma unroll
        for (int i = 0; i < 3; i++) qdst[t + i * TPB] = qsrc[t + i * TPB];
    }
    __syncthreads();

    unsigned long long X2[TQ], Y2[TQ], Z2[TQ];
    float mnlo[TQ], mnhi[TQ];
#pragma unroll
    for (int k = 0; k < TQ; k++) {
        int qi = t + k * TPB;                 // stride-3 LDS: gcd(3,32)=1, conflict-free
        float x = qsh[3*qi], y = qsh[3*qi+1], z = qsh[3*qi+2];
        X2[k] = pk2(x, x); Y2[k] = pk2(y, y); Z2[k] = pk2(z, z);
        mnlo[k] = __int_as_float(0x7f800000);
        mnhi[k] = __int_as_float(0x7f800000);
    }

#pragma unroll 2
    for (int p = 0; p < MC / 2; ++p) {
        float4 A  = tsh[2*p];
        float4 Bv = tsh[2*p + 1];
        unsigned long long NX = pk2(A.x,  A.y);
        unsigned long long NY = pk2(A.z,  A.w);
        unsigned long long NZ = pk2(Bv.x, Bv.y);
        unsigned long long H  = pk2(Bv.z, Bv.w);
        unsigned long long acc[TQ];
        // e = h - (xq*xt + yq*yt + zq*zt), two targets per packed op.
#pragma unroll
        for (int k = 0; k < TQ; k++)
            asm("fma.rn.f32x2 %0, %1, %2, %3;" : "=l"(acc[k]) : "l"(Z2[k]), "l"(NZ), "l"(H));
#pragma unroll
        for (int k = 0; k < TQ; k++)
            asm("fma.rn.f32x2 %0, %1, %2, %0;" : "+l"(acc[k]) : "l"(Y2[k]), "l"(NY));
#pragma unroll
        for (int k = 0; k < TQ; k++)
            asm("fma.rn.f32x2 %0, %1, %2, %0;" : "+l"(acc[k]) : "l"(X2[k]), "l"(NX));
#pragma unroll
        for (int k = 0; k < TQ; k++) {
            float lo, hi;
            asm("mov.b64 {%0,%1}, %2;" : "=f"(lo), "=f"(hi) : "l"(acc[k]));
            mnlo[k] = fminf(mnlo[k], lo);
            mnhi[k] = fminf(mnhi[k], hi);
        }
    }

#pragma unroll
    for (int k = 0; k < TQ; k++)
        atomicMax(&encOut[q0 + t + k * TPB],
                  ~fenc(fminf(mnlo[k], mnhi[k])));

    // ---- Grid-wide ticket reduction (last NSLICE CTAs do the sweep) ----
    __threadfence();
    if (t == 0) s_tk = atomicAdd(&g_tk1, 1u);
    __syncthreads();
    unsigned tk = s_tk;
    if (tk < NCTA - NSLICE) return;            // early CTAs are done

    // Wait until ALL 2048 CTAs have published their atomics (no deadlock:
    // every CTA reaches the increment above unconditionally before any spin).
    if (t == 0) { while (*(volatile unsigned*)&g_tk1 < (unsigned)NCTA) {} }
    __syncthreads();
    __threadfence();

    int slice = (int)tk - (NCTA - NSLICE);     // 0..63, deterministic slice content
    int base  = slice * (2 * ASZ / NSLICE);    // 1024 entries per slice
    float s = 0.f;
#pragma unroll
    for (int i = 0; i < 8; i++) {
        int idx   = base + t + i * TPB;        // 0..65535 = dir*32768 + pid
        int which = idx >> 15;
        int pid   = idx & (ASZ - 1);
        const float* raw = which ? q2 : q1;    // dir pairs with its query array
        unsigned u = g_enc[idx];
        float x = raw[3*pid], y = raw[3*pid+1], z = raw[3*pid+2];
        g_enc[idx] = 0u;                       // reset for next graph replay
        s += (x*x + y*y + z*z) + 2.0f * fdec(~u);
    }
#pragma unroll
    for (int o = 16; o > 0; o >>= 1) s += __shfl_down_sync(0xFFFFFFFFu, s, o);
    if ((t & 31) == 0) ws[t >> 5] = s;
    __syncthreads();
    if (t == 0) {
        g_part[slice] = (ws[0] + ws[1]) + (ws[2] + ws[3]);
        __threadfence();
        s_tk = atomicAdd(&g_tk2, 1u);
    }
    __syncthreads();

    if (s_tk == NSLICE - 1 && t < 32) {        // last slice CTA folds partials
        __threadfence();
        float v = g_part[t] + g_part[t + 32];
#pragma unroll
        for (int o = 16; o > 0; o >>= 1) v += __shfl_down_sync(0xFFFFFFFFu, v, o);
        if (t == 0) {
            out[0] = v * (1.0f / (float)(NB * NPTS));
            g_tk1 = 0u;                        // reset tickets for next replay
            g_tk2 = 0u;
        }
    }
}

extern "C" void kernel_launch(void* const* d_in, const int* in_sizes, int n_in,
                              void* d_out, int out_size) {
    const float* a1 = (const float*)d_in[0];   // array1 [4,8192,3]
    const float* a2 = (const float*)d_in[1];   // array2 [4,8192,3]
    float* out = (float*)d_out;

    dim3 grid(NPTS / QB, NPTS / MC, 2 * NB);   // (16,16,8) = 2048 CTAs
    chamfer_kernel<<<grid, TPB>>>(a1, a2, out);
}